// round 15
// baseline (speedup 1.0000x reference)
#include <cuda_runtime.h>
#include <cuda_fp16.h>
#include <math.h>
#include <stdint.h>

#define H     1024
#define INTER 4096
#define NE    8
#define TT    8192
#define LNEPS 1e-5f

#define BK2    64
#define RB     144
#define TB2    (128 * RB)            // 18432
#define STG2   (2 * TB2)             // 36864
#define SMEM2  (3 * STG2)            // 110592 (3-stage, 2 CTAs/SM)
#define STGA   (4 * TB2)             // 73728
#define SMEMA  (3 * STGA)            // 221184
#define MAXTILES 136
#define NPCTA  296                   // 2 CTAs/SM x 148 SMs, all resident

// ---------------- scratch (static device globals) ---------------------------
__device__ __half g_tnhh[(size_t)TT * H];
__device__ __half g_tnhl[(size_t)TT * H];
__device__ __half g_tnh[(size_t)TT * H];
__device__ __half g_acth[(size_t)TT * 2 * INTER];
__device__ __half g_oh[(size_t)TT * 2 * H];
__device__ int    g_cnt[NE];
__device__ int    g_list[NE * TT];
__device__ float  g_w[NE * TT];
__device__ int    g_tile_e[MAXTILES];
__device__ int    g_tile_bm[MAXTILES];
__device__ int    g_n1, g_n2;
__device__ int    g_work;
__device__ int    g_tdone[MAXTILES];
__device__ __half g_wh[(size_t)H * H];
__device__ __half g_wl[(size_t)H * H];
__device__ __half g_wgh[(size_t)NE * INTER * H];
__device__ __half g_wuh[(size_t)NE * INTER * H];
__device__ __half g_wdh[(size_t)NE * H * INTER];

// ---------------- helpers ---------------------------------------------------
__device__ __forceinline__ uint32_t smem_u32(const void* p) {
    uint32_t a;
    asm("{ .reg .u64 t; cvta.to.shared.u64 t, %1; cvt.u32.u64 %0, t; }" : "=r"(a) : "l"(p));
    return a;
}
__device__ __forceinline__ uint32_t pkhf(float lo, float hi) {
    uint32_t r;
    asm("cvt.rn.f16x2.f32 %0, %1, %2;" : "=r"(r) : "f"(hi), "f"(lo));
    return r;
}
__device__ __forceinline__ void cpasync16(uint32_t s, const void* g) {
    asm volatile("cp.async.cg.shared.global [%0], [%1], 16;" :: "r"(s), "l"(g));
}
#define CP_COMMIT() asm volatile("cp.async.commit_group;" ::: "memory")
#define CP_WAIT(n)  asm volatile("cp.async.wait_group %0;" :: "n"(n) : "memory")

__device__ __forceinline__ void ldsm4(uint32_t* r, uint32_t addr) {
    asm volatile("ldmatrix.sync.aligned.m8n8.x4.shared.b16 {%0,%1,%2,%3}, [%4];"
                 : "=r"(r[0]), "=r"(r[1]), "=r"(r[2]), "=r"(r[3]) : "r"(addr));
}
__device__ __forceinline__ void mma16f(float* c, const uint32_t* a, const uint32_t* b) {
    asm volatile(
        "mma.sync.aligned.m16n8k16.row.col.f32.f16.f16.f32 "
        "{%0,%1,%2,%3}, {%4,%5,%6,%7}, {%8,%9}, {%0,%1,%2,%3};"
        : "+f"(c[0]), "+f"(c[1]), "+f"(c[2]), "+f"(c[3])
        : "r"(a[0]), "r"(a[1]), "r"(a[2]), "r"(a[3]), "r"(b[0]), "r"(b[1]));
}

// ---------------------------------------------------------------------------
__global__ void __launch_bounds__(256) wconv_gu_k(const float4* __restrict__ sg,
                                                  const float4* __restrict__ su, int n4) {
    int i = blockIdx.x * blockDim.x + threadIdx.x;
    if (i >= n4) return;
    int which = blockIdx.y;
    const float4* s = (which == 0) ? sg : su;
    float4 v = s[i];
    uint2 o = { pkhf(v.x, v.y), pkhf(v.z, v.w) };
    __half* dst = (which == 0) ? g_wgh : g_wuh;
    ((uint2*)dst)[i] = o;
}
__global__ void __launch_bounds__(256) wconv_d_k(const float4* __restrict__ sd, int n4) {
    int i = blockIdx.x * blockDim.x + threadIdx.x;
    if (i >= n4) return;
    float4 v = sd[i];
    ((uint2*)g_wdh)[i] = { pkhf(v.x, v.y), pkhf(v.z, v.w) };
}

// attn_w fp32 -> hi/lo fp16 split; block 0 zeroes expert counters.
__global__ void __launch_bounds__(256) wsplit_k(const float4* __restrict__ s, int n4) {
    int i = blockIdx.x * blockDim.x + threadIdx.x;
    if (blockIdx.x == 0 && threadIdx.x < NE) g_cnt[threadIdx.x] = 0;
    if (i >= n4) return;
    float4 v = s[i];
    float hx = __half2float(__float2half_rn(v.x));
    float hy = __half2float(__float2half_rn(v.y));
    float hz = __half2float(__float2half_rn(v.z));
    float hw = __half2float(__float2half_rn(v.w));
    ((uint2*)g_wh)[i] = { pkhf(hx, hy), pkhf(hz, hw) };
    ((uint2*)g_wl)[i] = { pkhf(v.x - hx, v.y - hy), pkhf(v.z - hz, v.w - hw) };
}

// Build tile list; zero queue state for the persistent MoE kernel.
__global__ void __launch_bounds__(256) build_tiles_k() {
    int tid = threadIdx.x;
    if (tid < MAXTILES) g_tdone[tid] = 0;
    if (tid == 254) g_work = 0;
    if (tid == 0) {
        int n = 0;
#pragma unroll
        for (int e = 0; e < NE; ++e) {
            int t = (g_cnt[e] + 127) >> 7;
            for (int i = 0; i < t; ++i) { g_tile_e[n] = e; g_tile_bm[n] = i; ++n; }
        }
        g_n1 = n * 64;
        g_n2 = n * 8;
    }
}

__global__ void __launch_bounds__(256) ln1_kernel(const float* __restrict__ src,
                                                  const float* __restrict__ gamma,
                                                  const float* __restrict__ beta) {
    int row = blockIdx.x;
    int tid = threadIdx.x;
    const float4 xv = ((const float4*)(src + (size_t)row * H))[tid];
    float s = xv.x + xv.y + xv.z + xv.w;
    float q = xv.x * xv.x + xv.y * xv.y + xv.z * xv.z + xv.w * xv.w;
#pragma unroll
    for (int o = 16; o; o >>= 1) {
        s += __shfl_xor_sync(0xffffffffu, s, o);
        q += __shfl_xor_sync(0xffffffffu, q, o);
    }
    __shared__ float ss[8], sq[8];
    __shared__ float sm_, sr_;
    int w = tid >> 5;
    if ((tid & 31) == 0) { ss[w] = s; sq[w] = q; }
    __syncthreads();
    if (tid == 0) {
        float S = 0.f, Q = 0.f;
#pragma unroll
        for (int i = 0; i < 8; ++i) { S += ss[i]; Q += sq[i]; }
        float m = S * (1.0f / H);
        float v = Q * (1.0f / H) - m * m;
        sm_ = m;
        sr_ = rsqrtf(v + LNEPS);
    }
    __syncthreads();
    float m = sm_, r = sr_;
    const float4 gv = ((const float4*)gamma)[tid];
    const float4 bv = ((const float4*)beta)[tid];
    float4 o;
    o.x = (xv.x - m) * r * gv.x + bv.x;
    o.y = (xv.y - m) * r * gv.y + bv.y;
    o.z = (xv.z - m) * r * gv.z + bv.z;
    o.w = (xv.w - m) * r * gv.w + bv.w;
    float hx = __half2float(__float2half_rn(o.x));
    float hy = __half2float(__float2half_rn(o.y));
    float hz = __half2float(__float2half_rn(o.z));
    float hw = __half2float(__float2half_rn(o.w));
    ((uint2*)(g_tnhh + (size_t)row * H))[tid] = { pkhf(hx, hy), pkhf(hz, hw) };
    ((uint2*)(g_tnhl + (size_t)row * H))[tid] =
        { pkhf(o.x - hx, o.y - hy), pkhf(o.z - hz, o.w - hw) };
}

// LN2 fused with gate + top-2 + softmax + scatter.
__global__ void __launch_bounds__(256) ln2_gate_kernel(const float* __restrict__ src,
                                                       const float* __restrict__ gamma,
                                                       const float* __restrict__ beta,
                                                       const float* __restrict__ gw) {
    int row = blockIdx.x;
    int tid = threadIdx.x;
    const float4 xv = ((const float4*)(src + (size_t)row * H))[tid];
    float s = xv.x + xv.y + xv.z + xv.w;
    float q = xv.x * xv.x + xv.y * xv.y + xv.z * xv.z + xv.w * xv.w;
#pragma unroll
    for (int o = 16; o; o >>= 1) {
        s += __shfl_xor_sync(0xffffffffu, s, o);
        q += __shfl_xor_sync(0xffffffffu, q, o);
    }
    __shared__ float ss[8], sq[8];
    __shared__ float sm_, sr_;
    __shared__ float red[8][NE];
    int w = tid >> 5, lane = tid & 31;
    if (lane == 0) { ss[w] = s; sq[w] = q; }
    __syncthreads();
    if (tid == 0) {
        float S = 0.f, Q = 0.f;
#pragma unroll
        for (int i = 0; i < 8; ++i) { S += ss[i]; Q += sq[i]; }
        float m = S * (1.0f / H);
        float v = Q * (1.0f / H) - m * m;
        sm_ = m;
        sr_ = rsqrtf(v + LNEPS);
    }
    __syncthreads();
    float m = sm_, r = sr_;
    const float4 gv = ((const float4*)gamma)[tid];
    const float4 bv = ((const float4*)beta)[tid];
    float4 o;
    o.x = (xv.x - m) * r * gv.x + bv.x;
    o.y = (xv.y - m) * r * gv.y + bv.y;
    o.z = (xv.z - m) * r * gv.z + bv.z;
    o.w = (xv.w - m) * r * gv.w + bv.w;
    ((uint2*)(g_tnh + (size_t)row * H))[tid] = { pkhf(o.x, o.y), pkhf(o.z, o.w) };
    float part[NE];
#pragma unroll
    for (int e = 0; e < NE; ++e) {
        float4 g4 = ((const float4*)(gw + e * H))[tid];
        part[e] = o.x * g4.x + o.y * g4.y + o.z * g4.z + o.w * g4.w;
    }
#pragma unroll
    for (int off = 16; off; off >>= 1)
#pragma unroll
        for (int e = 0; e < NE; ++e) part[e] += __shfl_xor_sync(0xffffffffu, part[e], off);
    if (lane == 0)
#pragma unroll
        for (int e = 0; e < NE; ++e) red[w][e] = part[e];
    __syncthreads();
    if (tid == 0) {
        float lg[NE];
#pragma unroll
        for (int e = 0; e < NE; ++e) {
            float acc = 0.f;
#pragma unroll
            for (int i = 0; i < 8; ++i) acc += red[i][e];
            lg[e] = acc;
        }
        float v0 = -INFINITY; int i0 = 0;
#pragma unroll
        for (int e = 0; e < NE; ++e) if (lg[e] > v0) { v0 = lg[e]; i0 = e; }
        float v1 = -INFINITY; int i1 = 0;
#pragma unroll
        for (int e = 0; e < NE; ++e) if (e != i0 && lg[e] > v1) { v1 = lg[e]; i1 = e; }
        float ex = expf(v1 - v0);
        float w0 = 1.0f / (1.0f + ex);
        float w1 = ex / (1.0f + ex);
        int p0 = atomicAdd(&g_cnt[i0], 1);
        g_list[i0 * TT + p0] = row * 2 + 0;
        g_w[i0 * TT + p0] = w0;
        int p1 = atomicAdd(&g_cnt[i1], 1);
        g_list[i1 * TT + p1] = row * 2 + 1;
        g_w[i1 * TT + p1] = w1;
    }
}

extern __shared__ float smf[];

// ---------------------------------------------------------------------------
// attn (fp16 split, pipelined, 512 threads): C = X + tn @ W^T.
__global__ void __launch_bounds__(512) attn_f16(const float* __restrict__ X,
                                                float* __restrict__ C) {
    int tid = threadIdx.x;
    int bm = blockIdx.x, bn = blockIdx.y;
    int wid = tid >> 5, lane = tid & 31;
    int wm = (wid >> 2) * 32, wn = (wid & 3) * 32;

    const char* src8[8];
    uint32_t dst8[8];
#pragma unroll
    for (int i = 0; i < 8; ++i) {
        int f = tid + 512 * i;
        int t_ = f >> 10;
        int o = f & 1023;
        int r = o >> 3, q = o & 7;
        const __half* base =
            (t_ == 0) ? (g_tnhh + (size_t)(bm * 128 + r) * H) :
            (t_ == 1) ? (g_tnhl + (size_t)(bm * 128 + r) * H) :
            (t_ == 2) ? (g_wh + (size_t)(bn * 128 + r) * H) :
                        (g_wl + (size_t)(bn * 128 + r) * H);
        src8[i] = (const char*)base + q * 16;
        dst8[i] = (uint32_t)(t_ * TB2 + r * RB + q * 16);
    }
    uint32_t smb = smem_u32(smf);

    uint32_t aoff[2];
#pragma unroll
    for (int mt = 0; mt < 2; ++mt)
        aoff[mt] = (uint32_t)((wm + mt * 16 + (lane & 15)) * RB + ((lane >> 4) & 1) * 16);
    uint32_t boff[2];
#pragma unroll
    for (int p = 0; p < 2; ++p)
        boff[p] = (uint32_t)((wn + (2 * p + ((lane >> 3) >> 1)) * 8 + (lane & 7)) * RB +
                             ((lane >> 3) & 1) * 16);

    float acc[2][4][4] = {};

#define LOADA(st, c) do { \
    uint32_t bb_ = smb + (st) * STGA; \
    int kb_ = (c) * 128; \
    _Pragma("unroll") \
    for (int i_ = 0; i_ < 8; ++i_) \
        cpasync16(bb_ + dst8[i_], src8[i_] + kb_); \
    } while (0)

    LOADA(0, 0); CP_COMMIT();
    LOADA(1, 1); CP_COMMIT();
    const int NCH = H / BK2;  // 16
    for (int c = 0; c < NCH; ++c) {
        if (c < NCH - 1) { CP_WAIT(1); } else { CP_WAIT(0); }
        __syncthreads();
        if (c + 2 < NCH) { LOADA((c + 2) % 3, c + 2); CP_COMMIT(); }
        uint32_t sA = smb + (c % 3) * STGA;
#pragma unroll
        for (int ks = 0; ks < 4; ++ks) {
            uint32_t kb = ks * 32;
            uint32_t ah[2][4], al[2][4], bh[2][4], bl[2][4];
#pragma unroll
            for (int mt = 0; mt < 2; ++mt) {
                ldsm4(ah[mt], sA + aoff[mt] + kb);
                ldsm4(al[mt], sA + TB2 + aoff[mt] + kb);
            }
#pragma unroll
            for (int p = 0; p < 2; ++p) {
                ldsm4(bh[p], sA + 2 * TB2 + boff[p] + kb);
                ldsm4(bl[p], sA + 3 * TB2 + boff[p] + kb);
            }
#pragma unroll
            for (int nt = 0; nt < 4; ++nt) {
                const uint32_t* bhp = &bh[nt >> 1][(nt & 1) * 2];
                const uint32_t* blp = &bl[nt >> 1][(nt & 1) * 2];
#pragma unroll
                for (int mt = 0; mt < 2; ++mt) {
                    mma16f(acc[mt][nt], ah[mt], bhp);
                    mma16f(acc[mt][nt], ah[mt], blp);
                    mma16f(acc[mt][nt], al[mt], bhp);
                }
            }
        }
    }
#undef LOADA
    int g = lane >> 2, tc = lane & 3;
#pragma unroll
    for (int mt = 0; mt < 2; ++mt) {
        int row0 = bm * 128 + wm + mt * 16 + g;
#pragma unroll
        for (int nt = 0; nt < 4; ++nt) {
            int col = bn * 128 + wn + nt * 8 + 2 * tc;
            float2 x0 = *(const float2*)(X + (size_t)row0 * H + col);
            float2 o0 = { x0.x + acc[mt][nt][0], x0.y + acc[mt][nt][1] };
            *(float2*)(C + (size_t)row0 * H + col) = o0;
            float2 x1 = *(const float2*)(X + (size_t)(row0 + 8) * H + col);
            float2 o1 = { x1.x + acc[mt][nt][2], x1.y + acc[mt][nt][3] };
            *(float2*)(C + (size_t)(row0 + 8) * H + col) = o1;
        }
    }
}

// ---------------------------------------------------------------------------
// Persistent MoE kernel: one grid of NPCTA resident CTAs consumes an atomic
// work queue of [ntiles*64 mlp1 items, then ntiles*8 mlp2 items]. Per-tile
// readiness counters (release/acquire) order mlp2 after its tile's mlp1 work.
__device__ __forceinline__ void mlp1_body(int e, int bm, int ib, int tid) {
    __shared__ int sp[128];
    int cnt = g_cnt[e];
    if (tid < 128) {
        int r = bm * 128 + tid;
        sp[tid] = (r < cnt) ? g_list[e * TT + r] : -1;
    }
    __syncthreads();
    int wid = tid >> 5, lane = tid & 31;
    int wm = (wid >> 2) * 64, wn = (wid & 3) * 16;

    int lr0 = tid >> 3, q = tid & 7;
    const char* asrc[4];
    const char* bsrc[4];
#pragma unroll
    for (int i = 0; i < 4; ++i) {
        int r = lr0 + 32 * i;
        int p = sp[r];
        int t = (p < 0) ? 0 : (p >> 1);
        asrc[i] = (const char*)(g_tnh + (size_t)t * H) + q * 16;
        const __half* wsrc = (r < 64)
            ? (g_wgh + ((size_t)e * INTER + ib * 64 + r) * H)
            : (g_wuh + ((size_t)e * INTER + ib * 64 + (r - 64)) * H);
        bsrc[i] = (const char*)wsrc + q * 16;
    }
    uint32_t smb = smem_u32(smf);
    uint32_t dofs = (uint32_t)(lr0 * RB + q * 16);

    uint32_t aoff[4];
#pragma unroll
    for (int mt = 0; mt < 4; ++mt)
        aoff[mt] = (uint32_t)((wm + mt * 16 + (lane & 15)) * RB + ((lane >> 4) & 1) * 16);
    uint32_t boff = (uint32_t)((wn + ((lane >> 3) >> 1) * 8 + (lane & 7)) * RB +
                               ((lane >> 3) & 1) * 16);

    float accg[4][2][4] = {}, accu[4][2][4] = {};

#define LOAD1(st, c) do { \
    uint32_t bb_ = smb + (st) * STG2 + dofs; \
    int kb_ = (c) * 128; \
    _Pragma("unroll") \
    for (int i_ = 0; i_ < 4; ++i_) { \
        uint32_t d_ = bb_ + i_ * (32 * RB); \
        cpasync16(d_, asrc[i_] + kb_); \
        cpasync16(d_ + TB2, bsrc[i_] + kb_); \
    } } while (0)

    LOAD1(0, 0); CP_COMMIT();
    LOAD1(1, 1); CP_COMMIT();
    const int NCH = H / BK2;  // 16
    for (int c = 0; c < NCH; ++c) {
        if (c < NCH - 1) { CP_WAIT(1); } else { CP_WAIT(0); }
        __syncthreads();
        if (c + 2 < NCH) { LOAD1((c + 2) % 3, c + 2); CP_COMMIT(); }
        uint32_t sA = smb + (c % 3) * STG2;
        uint32_t sB = sA + TB2;
#pragma unroll
        for (int ks = 0; ks < 4; ++ks) {
            uint32_t kb = ks * 32;
            uint32_t a[4][4], bg[4], bu[4];
#pragma unroll
            for (int mt = 0; mt < 4; ++mt) ldsm4(a[mt], sA + aoff[mt] + kb);
            ldsm4(bg, sB + boff + kb);
            ldsm4(bu, sB + 64 * RB + boff + kb);
#pragma unroll
            for (int nt = 0; nt < 2; ++nt) {
#pragma unroll
                for (int mt = 0; mt < 4; ++mt) {
                    mma16f(accg[mt][nt], a[mt], &bg[nt * 2]);
                    mma16f(accu[mt][nt], a[mt], &bu[nt * 2]);
                }
            }
        }
    }
#undef LOAD1
    int g = lane >> 2, tc = lane & 3;
#pragma unroll
    for (int mt = 0; mt < 4; ++mt) {
        int r0 = wm + mt * 16 + g;
        int p0 = sp[r0], p1 = sp[r0 + 8];
#pragma unroll
        for (int nt = 0; nt < 2; ++nt) {
            int col = ib * 64 + wn + nt * 8 + 2 * tc;
            if (p0 >= 0) {
                float g0 = accg[mt][nt][0], u0 = accu[mt][nt][0];
                float g1 = accg[mt][nt][1], u1 = accu[mt][nt][1];
                uint32_t v = pkhf(g0 / (1.f + expf(-g0)) * u0,
                                  g1 / (1.f + expf(-g1)) * u1);
                *(uint32_t*)(g_acth + (size_t)p0 * INTER + col) = v;
            }
            if (p1 >= 0) {
                float g2 = accg[mt][nt][2], u2 = accu[mt][nt][2];
                float g3 = accg[mt][nt][3], u3 = accu[mt][nt][3];
                uint32_t v = pkhf(g2 / (1.f + expf(-g2)) * u2,
                                  g3 / (1.f + expf(-g3)) * u3);
                *(uint32_t*)(g_acth + (size_t)p1 * INTER + col) = v;
            }
        }
    }
}

__device__ __forceinline__ void mlp2_body(int e, int bm, int bn, int tid) {
    __shared__ int sp[128];
    __shared__ float sw[128];
    int cnt = g_cnt[e];
    if (tid < 128) {
        int r = bm * 128 + tid;
        int valid = (r < cnt);
        sp[tid] = valid ? g_list[e * TT + r] : -1;
        sw[tid] = valid ? g_w[e * TT + r] : 0.f;
    }
    __syncthreads();
    int wid = tid >> 5, lane = tid & 31;
    int wm = (wid >> 2) * 64, wn = (wid & 3) * 32;

    int lr0 = tid >> 3, q = tid & 7;
    const char* asrc[4];
    const char* bsrc[4];
#pragma unroll
    for (int i = 0; i < 4; ++i) {
        int r = lr0 + 32 * i;
        int p = sp[r];
        int pp = (p < 0) ? 0 : p;
        asrc[i] = (const char*)(g_acth + (size_t)pp * INTER) + q * 16;
        bsrc[i] = (const char*)(g_wdh + ((size_t)e * H + bn * 128 + r) * INTER) + q * 16;
    }
    uint32_t smb = smem_u32(smf);
    uint32_t dofs = (uint32_t)(lr0 * RB + q * 16);

    uint32_t aoff[4];
#pragma unroll
    for (int mt = 0; mt < 4; ++mt)
        aoff[mt] = (uint32_t)((wm + mt * 16 + (lane & 15)) * RB + ((lane >> 4) & 1) * 16);
    uint32_t boff[2];
#pragma unroll
    for (int p = 0; p < 2; ++p)
        boff[p] = (uint32_t)((wn + (2 * p + ((lane >> 3) >> 1)) * 8 + (lane & 7)) * RB +
                             ((lane >> 3) & 1) * 16);

    float acc[4][4][4] = {};

#define LOAD2(st, c) do { \
    uint32_t bb_ = smb + (st) * STG2 + dofs; \
    int kb_ = (c) * 128; \
    _Pragma("unroll") \
    for (int i_ = 0; i_ < 4; ++i_) { \
        uint32_t d_ = bb_ + i_ * (32 * RB); \
        cpasync16(d_, asrc[i_] + kb_); \
        cpasync16(d_ + TB2, bsrc[i_] + kb_); \
    } } while (0)

    LOAD2(0, 0); CP_COMMIT();
    LOAD2(1, 1); CP_COMMIT();
    const int NCH = INTER / BK2;  // 64
    for (int c = 0; c < NCH; ++c) {
        if (c < NCH - 1) { CP_WAIT(1); } else { CP_WAIT(0); }
        __syncthreads();
        if (c + 2 < NCH) { LOAD2((c + 2) % 3, c + 2); CP_COMMIT(); }
        uint32_t sA = smb + (c % 3) * STG2;
        uint32_t sB = sA + TB2;
#pragma unroll
        for (int ks = 0; ks < 4; ++ks) {
            uint32_t kb = ks * 32;
            uint32_t a[4][4], b[2][4];
#pragma unroll
            for (int mt = 0; mt < 4; ++mt) ldsm4(a[mt], sA + aoff[mt] + kb);
#pragma unroll
            for (int p = 0; p < 2; ++p) ldsm4(b[p], sB + boff[p] + kb);
#pragma unroll
            for (int nt = 0; nt < 4; ++nt) {
                const uint32_t* bp = &b[nt >> 1][(nt & 1) * 2];
#pragma unroll
                for (int mt = 0; mt < 4; ++mt) mma16f(acc[mt][nt], a[mt], bp);
            }
        }
    }
#undef LOAD2
    int g = lane >> 2, tc = lane & 3;
#pragma unroll
    for (int mt = 0; mt < 4; ++mt) {
        int r0 = wm + mt * 16 + g;
        int p0 = sp[r0], p1 = sp[r0 + 8];
        float w0 = sw[r0], w1 = sw[r0 + 8];
#pragma unroll
        for (int nt = 0; nt < 4; ++nt) {
            int col = bn * 128 + wn + nt * 8 + 2 * tc;
            if (p0 >= 0) {
                uint32_t v = pkhf(w0 * acc[mt][nt][0], w0 * acc[mt][nt][1]);
                *(uint32_t*)(g_oh + (size_t)p0 * H + col) = v;
            }
            if (p1 >= 0) {
                uint32_t v = pkhf(w1 * acc[mt][nt][2], w1 * acc[mt][nt][3]);
                *(uint32_t*)(g_oh + (size_t)p1 * H + col) = v;
            }
        }
    }
}

__global__ void __launch_bounds__(256, 2) moe_persist() {
    __shared__ int s_item;
    int tid = threadIdx.x;
    const int n1 = g_n1;
    const int ntot = n1 + g_n2;
    for (;;) {
        if (tid == 0) s_item = atomicAdd(&g_work, 1);
        __syncthreads();
        int item = s_item;
        __syncthreads();               // s_item safe to rewrite next iter
        if (item >= ntot) return;
        if (item < n1) {
            int tile = item >> 6, ib = item & 63;
            mlp1_body(g_tile_e[tile], g_tile_bm[tile], ib, tid);
            __threadfence();
            __syncthreads();
            if (tid == 0)
                asm volatile("red.release.gpu.global.add.s32 [%0], 1;"
                             :: "l"(&g_tdone[tile]) : "memory");
        } else {
            int it2 = item - n1;
            int tile = it2 >> 3, bn = it2 & 7;
            if (tid == 0) {
                int v;
                do {
                    asm volatile("ld.acquire.gpu.global.s32 %0, [%1];"
                                 : "=r"(v) : "l"(&g_tdone[tile]) : "memory");
                    if (v >= 64) break;
                    __nanosleep(128);
                } while (1);
            }
            __syncthreads();
            mlp2_body(g_tile_e[tile], g_tile_bm[tile], bn, tid);
            __syncthreads();
        }
    }
}

// out[t] += g_oh[2t] + g_oh[2t+1]
__global__ void __launch_bounds__(256) combine_kernel(float* __restrict__ C) {
    int v = blockIdx.x * blockDim.x + threadIdx.x;
    int t = v >> 8;
    int c = v & 255;
    const uint2* go = (const uint2*)g_oh;
    uint2 pa = go[(size_t)(2 * t) * 256 + c];
    uint2 pb = go[(size_t)(2 * t) * 256 + 256 + c];
    __half2 a0 = *(__half2*)&pa.x, a1 = *(__half2*)&pa.y;
    __half2 b0 = *(__half2*)&pb.x, b1 = *(__half2*)&pb.y;
    float2 fa0 = __half22float2(a0), fa1 = __half22float2(a1);
    float2 fb0 = __half22float2(b0), fb1 = __half22float2(b1);
    float4* out = (float4*)C;
    float4 o = out[v];
    o.x += fa0.x + fb0.x; o.y += fa0.y + fb0.y;
    o.z += fa1.x + fb1.x; o.w += fa1.y + fb1.y;
    out[v] = o;
}

// ---------------------------------------------------------------------------
extern "C" void kernel_launch(void* const* d_in, const int* in_sizes, int n_in,
                              void* d_out, int out_size) {
    const float* x         = (const float*)d_in[0];
    const float* ln1_g     = (const float*)d_in[1];
    const float* ln1_b     = (const float*)d_in[2];
    const float* attn_w    = (const float*)d_in[3];
    const float* ln2_g     = (const float*)d_in[4];
    const float* ln2_b     = (const float*)d_in[5];
    const float* gate_w    = (const float*)d_in[6];
    const float* gate_proj = (const float*)d_in[7];
    const float* up_proj   = (const float*)d_in[8];
    const float* down_proj = (const float*)d_in[9];
    float* out = (float*)d_out;

    cudaFuncSetAttribute(attn_f16,    cudaFuncAttributeMaxDynamicSharedMemorySize, SMEMA);
    cudaFuncSetAttribute(moe_persist, cudaFuncAttributeMaxDynamicSharedMemorySize, SMEM2);

    const int n4w = NE * INTER * H / 4;  // 8388608
    const int n4a = H * H / 4;           // 262144

    // Side stream: wsplit(+cnt zero) -> wconv gate/up -> wconv down.
    cudaStream_t s1;
    cudaStreamCreateWithFlags(&s1, cudaStreamNonBlocking);
    cudaEvent_t e0, eA, eW;
    cudaEventCreateWithFlags(&e0, cudaEventDisableTiming);
    cudaEventCreateWithFlags(&eA, cudaEventDisableTiming);
    cudaEventCreateWithFlags(&eW, cudaEventDisableTiming);

    cudaEventRecord(e0, 0);
    cudaStreamWaitEvent(s1, e0, 0);
    wsplit_k<<<n4a / 256, 256, 0, s1>>>((const float4*)attn_w, n4a);
    cudaEventRecord(eA, s1);
    wconv_gu_k<<<dim3(n4w / 256, 2), 256, 0, s1>>>((const float4*)gate_proj,
                                                   (const float4*)up_proj, n4w);
    wconv_d_k<<<n4w / 256, 256, 0, s1>>>((const float4*)down_proj, n4w);
    cudaEventRecord(eW, s1);

    ln1_kernel<<<TT, 256>>>(x, ln1_g, ln1_b);
    cudaStreamWaitEvent(0, eA, 0);
    attn_f16<<<dim3(TT / 128, H / 128), 512, SMEMA>>>(x, out);
    ln2_gate_kernel<<<TT, 256>>>(out, ln2_g, ln2_b, gate_w);
    build_tiles_k<<<1, 256>>>();
    cudaStreamWaitEvent(0, eW, 0);
    moe_persist<<<NPCTA, 256, SMEM2>>>();
    combine_kernel<<<(TT * H / 4) / 256, 256>>>(out);
}

// round 16
// speedup vs baseline: 1.0855x; 1.0855x over previous
#include <cuda_runtime.h>
#include <cuda_fp16.h>
#include <math.h>
#include <stdint.h>

#define H     1024
#define INTER 4096
#define NE    8
#define TT    8192
#define LNEPS 1e-5f

// fp16 tiling: 64-half K chunks, 144B padded rows
#define BK2    64
#define RB     144                   // bytes per smem row (64*2 + 16 pad)
#define TB2    (128 * RB)            // 18432 bytes per 128-row tile
#define STG2   (2 * TB2)             // mlp stage: A + B = 36864
#define SMEM2  (3 * STG2)            // 110592 (3-stage, 2 CTAs/SM)
#define STGA   (4 * TB2)             // attn stage: Ah, Al, Bh, Bl = 73728
#define SMEMA  (3 * STGA)            // 221184
#define MAXTILES 136

// ---------------- scratch (static device globals) ---------------------------
__device__ __half g_tnhh[(size_t)TT * H];                // LN1 out hi fp16
__device__ __half g_tnhl[(size_t)TT * H];                // LN1 out lo fp16
__device__ __half g_tnh[(size_t)TT * H];                 // LN2 out fp16
__device__ __half g_acth[(size_t)TT * 2 * INTER];        // silu(g)*u fp16 per pair
__device__ __half g_oh[(size_t)TT * 2 * H];              // per-pair weighted down out (fp16)
__device__ int    g_cnt[NE];
__device__ int    g_list[NE * TT];
__device__ float  g_w[NE * TT];
__device__ int    g_tile_e[MAXTILES];
__device__ int    g_tile_bm[MAXTILES];
__device__ int    g_ntiles;
__device__ __half g_wh[(size_t)H * H];                   // attn_w hi fp16
__device__ __half g_wl[(size_t)H * H];                   // attn_w lo fp16
__device__ __half g_wgh[(size_t)NE * INTER * H];         // fp16 weight copies
__device__ __half g_wuh[(size_t)NE * INTER * H];
__device__ __half g_wdh[(size_t)NE * H * INTER];

// ---------------- helpers ---------------------------------------------------
__device__ __forceinline__ uint32_t smem_u32(const void* p) {
    uint32_t a;
    asm("{ .reg .u64 t; cvta.to.shared.u64 t, %1; cvt.u32.u64 %0, t; }" : "=r"(a) : "l"(p));
    return a;
}
__device__ __forceinline__ uint32_t pkhf(float lo, float hi) {
    uint32_t r;
    asm("cvt.rn.f16x2.f32 %0, %1, %2;" : "=r"(r) : "f"(hi), "f"(lo));
    return r;
}
__device__ __forceinline__ void cpasync16(uint32_t s, const void* g) {
    asm volatile("cp.async.cg.shared.global [%0], [%1], 16;" :: "r"(s), "l"(g));
}
#define CP_COMMIT() asm volatile("cp.async.commit_group;" ::: "memory")
#define CP_WAIT(n)  asm volatile("cp.async.wait_group %0;" :: "n"(n) : "memory")

__device__ __forceinline__ void ldsm4(uint32_t* r, uint32_t addr) {
    asm volatile("ldmatrix.sync.aligned.m8n8.x4.shared.b16 {%0,%1,%2,%3}, [%4];"
                 : "=r"(r[0]), "=r"(r[1]), "=r"(r[2]), "=r"(r[3]) : "r"(addr));
}
__device__ __forceinline__ void mma16f(float* c, const uint32_t* a, const uint32_t* b) {
    asm volatile(
        "mma.sync.aligned.m16n8k16.row.col.f32.f16.f16.f32 "
        "{%0,%1,%2,%3}, {%4,%5,%6,%7}, {%8,%9}, {%0,%1,%2,%3};"
        : "+f"(c[0]), "+f"(c[1]), "+f"(c[2]), "+f"(c[3])
        : "r"(a[0]), "r"(a[1]), "r"(a[2]), "r"(a[3]), "r"(b[0]), "r"(b[1]));
}

// ---------------------------------------------------------------------------
// MoE weight conversion, split by consumer. which: 0=gate, 1=up (pre-mlp1).
__global__ void __launch_bounds__(256) wconv_gu_k(const float4* __restrict__ sg,
                                                  const float4* __restrict__ su, int n4) {
    int i = blockIdx.x * blockDim.x + threadIdx.x;
    if (i >= n4) return;
    int which = blockIdx.y;
    const float4* s = (which == 0) ? sg : su;
    float4 v = s[i];
    uint2 o = { pkhf(v.x, v.y), pkhf(v.z, v.w) };
    __half* dst = (which == 0) ? g_wgh : g_wuh;
    ((uint2*)dst)[i] = o;
}
__global__ void __launch_bounds__(256) wconv_d_k(const float4* __restrict__ sd, int n4) {
    int i = blockIdx.x * blockDim.x + threadIdx.x;
    if (i >= n4) return;
    float4 v = sd[i];
    ((uint2*)g_wdh)[i] = { pkhf(v.x, v.y), pkhf(v.z, v.w) };
}

// attn_w fp32 -> hi/lo fp16 split; also zeroes expert counters (block 0).
__global__ void __launch_bounds__(256) wsplit_k(const float4* __restrict__ s, int n4) {
    int i = blockIdx.x * blockDim.x + threadIdx.x;
    if (blockIdx.x == 0 && threadIdx.x < NE) g_cnt[threadIdx.x] = 0;
    if (i >= n4) return;
    float4 v = s[i];
    float hx = __half2float(__float2half_rn(v.x));
    float hy = __half2float(__float2half_rn(v.y));
    float hz = __half2float(__float2half_rn(v.z));
    float hw = __half2float(__float2half_rn(v.w));
    ((uint2*)g_wh)[i] = { pkhf(hx, hy), pkhf(hz, hw) };
    ((uint2*)g_wl)[i] = { pkhf(v.x - hx, v.y - hy), pkhf(v.z - hz, v.w - hw) };
}

// Build compact (expert, bm) tile list from g_cnt.
__global__ void build_tiles_k() {
    if (threadIdx.x == 0) {
        int n = 0;
#pragma unroll
        for (int e = 0; e < NE; ++e) {
            int t = (g_cnt[e] + 127) >> 7;
            for (int i = 0; i < t; ++i) { g_tile_e[n] = e; g_tile_bm[n] = i; ++n; }
        }
        g_ntiles = n;
    }
}

__global__ void __launch_bounds__(256) ln1_kernel(const float* __restrict__ src,
                                                  const float* __restrict__ gamma,
                                                  const float* __restrict__ beta) {
    int row = blockIdx.x;
    int tid = threadIdx.x;
    const float4 xv = ((const float4*)(src + (size_t)row * H))[tid];
    float s = xv.x + xv.y + xv.z + xv.w;
    float q = xv.x * xv.x + xv.y * xv.y + xv.z * xv.z + xv.w * xv.w;
#pragma unroll
    for (int o = 16; o; o >>= 1) {
        s += __shfl_xor_sync(0xffffffffu, s, o);
        q += __shfl_xor_sync(0xffffffffu, q, o);
    }
    __shared__ float ss[8], sq[8];
    __shared__ float sm_, sr_;
    int w = tid >> 5;
    if ((tid & 31) == 0) { ss[w] = s; sq[w] = q; }
    __syncthreads();
    if (tid == 0) {
        float S = 0.f, Q = 0.f;
#pragma unroll
        for (int i = 0; i < 8; ++i) { S += ss[i]; Q += sq[i]; }
        float m = S * (1.0f / H);
        float v = Q * (1.0f / H) - m * m;
        sm_ = m;
        sr_ = rsqrtf(v + LNEPS);
    }
    __syncthreads();
    float m = sm_, r = sr_;
    const float4 gv = ((const float4*)gamma)[tid];
    const float4 bv = ((const float4*)beta)[tid];
    float4 o;
    o.x = (xv.x - m) * r * gv.x + bv.x;
    o.y = (xv.y - m) * r * gv.y + bv.y;
    o.z = (xv.z - m) * r * gv.z + bv.z;
    o.w = (xv.w - m) * r * gv.w + bv.w;
    float hx = __half2float(__float2half_rn(o.x));
    float hy = __half2float(__float2half_rn(o.y));
    float hz = __half2float(__float2half_rn(o.z));
    float hw = __half2float(__float2half_rn(o.w));
    ((uint2*)(g_tnhh + (size_t)row * H))[tid] = { pkhf(hx, hy), pkhf(hz, hw) };
    ((uint2*)(g_tnhl + (size_t)row * H))[tid] =
        { pkhf(o.x - hx, o.y - hy), pkhf(o.z - hz, o.w - hw) };
}

// LN2 fused with gate + top-2 + softmax + scatter.
__global__ void __launch_bounds__(256) ln2_gate_kernel(const float* __restrict__ src,
                                                       const float* __restrict__ gamma,
                                                       const float* __restrict__ beta,
                                                       const float* __restrict__ gw) {
    int row = blockIdx.x;
    int tid = threadIdx.x;
    const float4 xv = ((const float4*)(src + (size_t)row * H))[tid];
    float s = xv.x + xv.y + xv.z + xv.w;
    float q = xv.x * xv.x + xv.y * xv.y + xv.z * xv.z + xv.w * xv.w;
#pragma unroll
    for (int o = 16; o; o >>= 1) {
        s += __shfl_xor_sync(0xffffffffu, s, o);
        q += __shfl_xor_sync(0xffffffffu, q, o);
    }
    __shared__ float ss[8], sq[8];
    __shared__ float sm_, sr_;
    __shared__ float red[8][NE];
    int w = tid >> 5, lane = tid & 31;
    if (lane == 0) { ss[w] = s; sq[w] = q; }
    __syncthreads();
    if (tid == 0) {
        float S = 0.f, Q = 0.f;
#pragma unroll
        for (int i = 0; i < 8; ++i) { S += ss[i]; Q += sq[i]; }
        float m = S * (1.0f / H);
        float v = Q * (1.0f / H) - m * m;
        sm_ = m;
        sr_ = rsqrtf(v + LNEPS);
    }
    __syncthreads();
    float m = sm_, r = sr_;
    const float4 gv = ((const float4*)gamma)[tid];
    const float4 bv = ((const float4*)beta)[tid];
    float4 o;
    o.x = (xv.x - m) * r * gv.x + bv.x;
    o.y = (xv.y - m) * r * gv.y + bv.y;
    o.z = (xv.z - m) * r * gv.z + bv.z;
    o.w = (xv.w - m) * r * gv.w + bv.w;
    ((uint2*)(g_tnh + (size_t)row * H))[tid] = { pkhf(o.x, o.y), pkhf(o.z, o.w) };
    float part[NE];
#pragma unroll
    for (int e = 0; e < NE; ++e) {
        float4 g4 = ((const float4*)(gw + e * H))[tid];
        part[e] = o.x * g4.x + o.y * g4.y + o.z * g4.z + o.w * g4.w;
    }
#pragma unroll
    for (int off = 16; off; off >>= 1)
#pragma unroll
        for (int e = 0; e < NE; ++e) part[e] += __shfl_xor_sync(0xffffffffu, part[e], off);
    if (lane == 0)
#pragma unroll
        for (int e = 0; e < NE; ++e) red[w][e] = part[e];
    __syncthreads();
    if (tid == 0) {
        float lg[NE];
#pragma unroll
        for (int e = 0; e < NE; ++e) {
            float acc = 0.f;
#pragma unroll
            for (int i = 0; i < 8; ++i) acc += red[i][e];
            lg[e] = acc;
        }
        float v0 = -INFINITY; int i0 = 0;
#pragma unroll
        for (int e = 0; e < NE; ++e) if (lg[e] > v0) { v0 = lg[e]; i0 = e; }
        float v1 = -INFINITY; int i1 = 0;
#pragma unroll
        for (int e = 0; e < NE; ++e) if (e != i0 && lg[e] > v1) { v1 = lg[e]; i1 = e; }
        float ex = expf(v1 - v0);
        float w0 = 1.0f / (1.0f + ex);
        float w1 = ex / (1.0f + ex);
        int p0 = atomicAdd(&g_cnt[i0], 1);
        g_list[i0 * TT + p0] = row * 2 + 0;
        g_w[i0 * TT + p0] = w0;
        int p1 = atomicAdd(&g_cnt[i1], 1);
        g_list[i1 * TT + p1] = row * 2 + 1;
        g_w[i1 * TT + p1] = w1;
    }
}

extern __shared__ float smf[];

// ---------------------------------------------------------------------------
// attn (fp16 split, pipelined, 512 threads / 16 warps): C = X + tn @ W^T.
__global__ void __launch_bounds__(512) attn_f16(const float* __restrict__ X,
                                                float* __restrict__ C) {
    int tid = threadIdx.x;
    int bm = blockIdx.x, bn = blockIdx.y;
    int wid = tid >> 5, lane = tid & 31;
    int wm = (wid >> 2) * 32, wn = (wid & 3) * 32;

    const char* src8[8];
    uint32_t dst8[8];
#pragma unroll
    for (int i = 0; i < 8; ++i) {
        int f = tid + 512 * i;
        int t_ = f >> 10;
        int o = f & 1023;
        int r = o >> 3, q = o & 7;
        const __half* base =
            (t_ == 0) ? (g_tnhh + (size_t)(bm * 128 + r) * H) :
            (t_ == 1) ? (g_tnhl + (size_t)(bm * 128 + r) * H) :
            (t_ == 2) ? (g_wh + (size_t)(bn * 128 + r) * H) :
                        (g_wl + (size_t)(bn * 128 + r) * H);
        src8[i] = (const char*)base + q * 16;
        dst8[i] = (uint32_t)(t_ * TB2 + r * RB + q * 16);
    }
    uint32_t smb = smem_u32(smf);

    uint32_t aoff[2];
#pragma unroll
    for (int mt = 0; mt < 2; ++mt)
        aoff[mt] = (uint32_t)((wm + mt * 16 + (lane & 15)) * RB + ((lane >> 4) & 1) * 16);
    uint32_t boff[2];
#pragma unroll
    for (int p = 0; p < 2; ++p)
        boff[p] = (uint32_t)((wn + (2 * p + ((lane >> 3) >> 1)) * 8 + (lane & 7)) * RB +
                             ((lane >> 3) & 1) * 16);

    float acc[2][4][4] = {};

#define LOADA(st, c) do { \
    uint32_t bb_ = smb + (st) * STGA; \
    int kb_ = (c) * 128; \
    _Pragma("unroll") \
    for (int i_ = 0; i_ < 8; ++i_) \
        cpasync16(bb_ + dst8[i_], src8[i_] + kb_); \
    } while (0)

    LOADA(0, 0); CP_COMMIT();
    LOADA(1, 1); CP_COMMIT();
    const int NCH = H / BK2;  // 16
    for (int c = 0; c < NCH; ++c) {
        if (c < NCH - 1) { CP_WAIT(1); } else { CP_WAIT(0); }
        __syncthreads();
        if (c + 2 < NCH) { LOADA((c + 2) % 3, c + 2); CP_COMMIT(); }
        uint32_t sA = smb + (c % 3) * STGA;
#pragma unroll
        for (int ks = 0; ks < 4; ++ks) {
            uint32_t kb = ks * 32;
            uint32_t ah[2][4], al[2][4], bh[2][4], bl[2][4];
#pragma unroll
            for (int mt = 0; mt < 2; ++mt) {
                ldsm4(ah[mt], sA + aoff[mt] + kb);
                ldsm4(al[mt], sA + TB2 + aoff[mt] + kb);
            }
#pragma unroll
            for (int p = 0; p < 2; ++p) {
                ldsm4(bh[p], sA + 2 * TB2 + boff[p] + kb);
                ldsm4(bl[p], sA + 3 * TB2 + boff[p] + kb);
            }
#pragma unroll
            for (int nt = 0; nt < 4; ++nt) {
                const uint32_t* bhp = &bh[nt >> 1][(nt & 1) * 2];
                const uint32_t* blp = &bl[nt >> 1][(nt & 1) * 2];
#pragma unroll
                for (int mt = 0; mt < 2; ++mt) {
                    mma16f(acc[mt][nt], ah[mt], bhp);
                    mma16f(acc[mt][nt], ah[mt], blp);
                    mma16f(acc[mt][nt], al[mt], bhp);
                }
            }
        }
    }
#undef LOADA
    int g = lane >> 2, tc = lane & 3;
#pragma unroll
    for (int mt = 0; mt < 2; ++mt) {
        int row0 = bm * 128 + wm + mt * 16 + g;
#pragma unroll
        for (int nt = 0; nt < 4; ++nt) {
            int col = bn * 128 + wn + nt * 8 + 2 * tc;
            float2 x0 = *(const float2*)(X + (size_t)row0 * H + col);
            float2 o0 = { x0.x + acc[mt][nt][0], x0.y + acc[mt][nt][1] };
            *(float2*)(C + (size_t)row0 * H + col) = o0;
            float2 x1 = *(const float2*)(X + (size_t)(row0 + 8) * H + col);
            float2 o1 = { x1.x + acc[mt][nt][2], x1.y + acc[mt][nt][3] };
            *(float2*)(C + (size_t)(row0 + 8) * H + col) = o1;
        }
    }
}

// ---------------------------------------------------------------------------
// mlp1 (fp16, R7 config + tile list): CTA 128 pairs x 64 inter.
__global__ void __launch_bounds__(256, 2) mlp1_tc() {
    if (blockIdx.x >= g_ntiles) return;
    int e = g_tile_e[blockIdx.x];
    int bm = g_tile_bm[blockIdx.x];
    int cnt = g_cnt[e];
    int ib = blockIdx.y;
    __shared__ int sp[128];
    int tid = threadIdx.x;
    if (tid < 128) {
        int r = bm * 128 + tid;
        sp[tid] = (r < cnt) ? g_list[e * TT + r] : -1;
    }
    __syncthreads();
    int wid = tid >> 5, lane = tid & 31;
    int wm = (wid >> 2) * 64, wn = (wid & 3) * 16;

    int lr0 = tid >> 3, q = tid & 7;
    const char* asrc[4];
    const char* bsrc[4];
#pragma unroll
    for (int i = 0; i < 4; ++i) {
        int r = lr0 + 32 * i;
        int p = sp[r];
        int t = (p < 0) ? 0 : (p >> 1);
        asrc[i] = (const char*)(g_tnh + (size_t)t * H) + q * 16;
        const __half* wsrc = (r < 64)
            ? (g_wgh + ((size_t)e * INTER + ib * 64 + r) * H)
            : (g_wuh + ((size_t)e * INTER + ib * 64 + (r - 64)) * H);
        bsrc[i] = (const char*)wsrc + q * 16;
    }
    uint32_t smb = smem_u32(smf);
    uint32_t dofs = (uint32_t)(lr0 * RB + q * 16);

    uint32_t aoff[4];
#pragma unroll
    for (int mt = 0; mt < 4; ++mt)
        aoff[mt] = (uint32_t)((wm + mt * 16 + (lane & 15)) * RB + ((lane >> 4) & 1) * 16);
    uint32_t boff = (uint32_t)((wn + ((lane >> 3) >> 1) * 8 + (lane & 7)) * RB +
                               ((lane >> 3) & 1) * 16);

    float accg[4][2][4] = {}, accu[4][2][4] = {};

#define LOAD1(st, c) do { \
    uint32_t bb_ = smb + (st) * STG2 + dofs; \
    int kb_ = (c) * 128; \
    _Pragma("unroll") \
    for (int i_ = 0; i_ < 4; ++i_) { \
        uint32_t d_ = bb_ + i_ * (32 * RB); \
        cpasync16(d_, asrc[i_] + kb_); \
        cpasync16(d_ + TB2, bsrc[i_] + kb_); \
    } } while (0)

    LOAD1(0, 0); CP_COMMIT();
    LOAD1(1, 1); CP_COMMIT();
    const int NCH = H / BK2;  // 16
    for (int c = 0; c < NCH; ++c) {
        if (c < NCH - 1) { CP_WAIT(1); } else { CP_WAIT(0); }
        __syncthreads();
        if (c + 2 < NCH) { LOAD1((c + 2) % 3, c + 2); CP_COMMIT(); }
        uint32_t sA = smb + (c % 3) * STG2;
        uint32_t sB = sA + TB2;
#pragma unroll
        for (int ks = 0; ks < 4; ++ks) {
            uint32_t kb = ks * 32;
            uint32_t a[4][4], bg[4], bu[4];
#pragma unroll
            for (int mt = 0; mt < 4; ++mt) ldsm4(a[mt], sA + aoff[mt] + kb);
            ldsm4(bg, sB + boff + kb);
            ldsm4(bu, sB + 64 * RB + boff + kb);
#pragma unroll
            for (int nt = 0; nt < 2; ++nt) {
#pragma unroll
                for (int mt = 0; mt < 4; ++mt) {
                    mma16f(accg[mt][nt], a[mt], &bg[nt * 2]);
                    mma16f(accu[mt][nt], a[mt], &bu[nt * 2]);
                }
            }
        }
    }
#undef LOAD1
    int g = lane >> 2, tc = lane & 3;
#pragma unroll
    for (int mt = 0; mt < 4; ++mt) {
        int r0 = wm + mt * 16 + g;
        int p0 = sp[r0], p1 = sp[r0 + 8];
#pragma unroll
        for (int nt = 0; nt < 2; ++nt) {
            int col = ib * 64 + wn + nt * 8 + 2 * tc;
            if (p0 >= 0) {
                float g0 = accg[mt][nt][0], u0 = accu[mt][nt][0];
                float g1 = accg[mt][nt][1], u1 = accu[mt][nt][1];
                uint32_t v = pkhf(g0 / (1.f + expf(-g0)) * u0,
                                  g1 / (1.f + expf(-g1)) * u1);
                *(uint32_t*)(g_acth + (size_t)p0 * INTER + col) = v;
            }
            if (p1 >= 0) {
                float g2 = accg[mt][nt][2], u2 = accu[mt][nt][2];
                float g3 = accg[mt][nt][3], u3 = accu[mt][nt][3];
                uint32_t v = pkhf(g2 / (1.f + expf(-g2)) * u2,
                                  g3 / (1.f + expf(-g3)) * u3);
                *(uint32_t*)(g_acth + (size_t)p1 * INTER + col) = v;
            }
        }
    }
}

// ---------------------------------------------------------------------------
// mlp2 (fp16, R7 config + tile list): CTA 128 pairs x 128 H cols, K=INTER.
__global__ void __launch_bounds__(256, 2) mlp2_tc() {
    if (blockIdx.x >= g_ntiles) return;
    int e = g_tile_e[blockIdx.x];
    int bm = g_tile_bm[blockIdx.x];
    int cnt = g_cnt[e];
    int bn = blockIdx.y;
    __shared__ int sp[128];
    __shared__ float sw[128];
    int tid = threadIdx.x;
    if (tid < 128) {
        int r = bm * 128 + tid;
        int valid = (r < cnt);
        sp[tid] = valid ? g_list[e * TT + r] : -1;
        sw[tid] = valid ? g_w[e * TT + r] : 0.f;
    }
    __syncthreads();
    int wid = tid >> 5, lane = tid & 31;
    int wm = (wid >> 2) * 64, wn = (wid & 3) * 32;

    int lr0 = tid >> 3, q = tid & 7;
    const char* asrc[4];
    const char* bsrc[4];
#pragma unroll
    for (int i = 0; i < 4; ++i) {
        int r = lr0 + 32 * i;
        int p = sp[r];
        int pp = (p < 0) ? 0 : p;
        asrc[i] = (const char*)(g_acth + (size_t)pp * INTER) + q * 16;
        bsrc[i] = (const char*)(g_wdh + ((size_t)e * H + bn * 128 + r) * INTER) + q * 16;
    }
    uint32_t smb = smem_u32(smf);
    uint32_t dofs = (uint32_t)(lr0 * RB + q * 16);

    uint32_t aoff[4];
#pragma unroll
    for (int mt = 0; mt < 4; ++mt)
        aoff[mt] = (uint32_t)((wm + mt * 16 + (lane & 15)) * RB + ((lane >> 4) & 1) * 16);
    uint32_t boff[2];
#pragma unroll
    for (int p = 0; p < 2; ++p)
        boff[p] = (uint32_t)((wn + (2 * p + ((lane >> 3) >> 1)) * 8 + (lane & 7)) * RB +
                             ((lane >> 3) & 1) * 16);

    float acc[4][4][4] = {};

#define LOAD2(st, c) do { \
    uint32_t bb_ = smb + (st) * STG2 + dofs; \
    int kb_ = (c) * 128; \
    _Pragma("unroll") \
    for (int i_ = 0; i_ < 4; ++i_) { \
        uint32_t d_ = bb_ + i_ * (32 * RB); \
        cpasync16(d_, asrc[i_] + kb_); \
        cpasync16(d_ + TB2, bsrc[i_] + kb_); \
    } } while (0)

    LOAD2(0, 0); CP_COMMIT();
    LOAD2(1, 1); CP_COMMIT();
    const int NCH = INTER / BK2;  // 64
    for (int c = 0; c < NCH; ++c) {
        if (c < NCH - 1) { CP_WAIT(1); } else { CP_WAIT(0); }
        __syncthreads();
        if (c + 2 < NCH) { LOAD2((c + 2) % 3, c + 2); CP_COMMIT(); }
        uint32_t sA = smb + (c % 3) * STG2;
        uint32_t sB = sA + TB2;
#pragma unroll
        for (int ks = 0; ks < 4; ++ks) {
            uint32_t kb = ks * 32;
            uint32_t a[4][4], b[2][4];
#pragma unroll
            for (int mt = 0; mt < 4; ++mt) ldsm4(a[mt], sA + aoff[mt] + kb);
#pragma unroll
            for (int p = 0; p < 2; ++p) ldsm4(b[p], sB + boff[p] + kb);
#pragma unroll
            for (int nt = 0; nt < 4; ++nt) {
                const uint32_t* bp = &b[nt >> 1][(nt & 1) * 2];
#pragma unroll
                for (int mt = 0; mt < 4; ++mt) mma16f(acc[mt][nt], a[mt], bp);
            }
        }
    }
#undef LOAD2
    int g = lane >> 2, tc = lane & 3;
#pragma unroll
    for (int mt = 0; mt < 4; ++mt) {
        int r0 = wm + mt * 16 + g;
        int p0 = sp[r0], p1 = sp[r0 + 8];
        float w0 = sw[r0], w1 = sw[r0 + 8];
#pragma unroll
        for (int nt = 0; nt < 4; ++nt) {
            int col = bn * 128 + wn + nt * 8 + 2 * tc;
            if (p0 >= 0) {
                uint32_t v = pkhf(w0 * acc[mt][nt][0], w0 * acc[mt][nt][1]);
                *(uint32_t*)(g_oh + (size_t)p0 * H + col) = v;
            }
            if (p1 >= 0) {
                uint32_t v = pkhf(w1 * acc[mt][nt][2], w1 * acc[mt][nt][3]);
                *(uint32_t*)(g_oh + (size_t)p1 * H + col) = v;
            }
        }
    }
}

// out[t] += g_oh[2t] + g_oh[2t+1]  (fp16 per-pair partials)
__global__ void __launch_bounds__(256) combine_kernel(float* __restrict__ C) {
    int v = blockIdx.x * blockDim.x + threadIdx.x;
    int t = v >> 8;
    int c = v & 255;
    const uint2* go = (const uint2*)g_oh;
    uint2 pa = go[(size_t)(2 * t) * 256 + c];
    uint2 pb = go[(size_t)(2 * t) * 256 + 256 + c];
    __half2 a0 = *(__half2*)&pa.x, a1 = *(__half2*)&pa.y;
    __half2 b0 = *(__half2*)&pb.x, b1 = *(__half2*)&pb.y;
    float2 fa0 = __half22float2(a0), fa1 = __half22float2(a1);
    float2 fb0 = __half22float2(b0), fb1 = __half22float2(b1);
    float4* out = (float4*)C;
    float4 o = out[v];
    o.x += fa0.x + fb0.x; o.y += fa0.y + fb0.y;
    o.z += fa1.x + fb1.x; o.w += fa1.y + fb1.y;
    out[v] = o;
}

// ---------------------------------------------------------------------------
extern "C" void kernel_launch(void* const* d_in, const int* in_sizes, int n_in,
                              void* d_out, int out_size) {
    const float* x         = (const float*)d_in[0];
    const float* ln1_g     = (const float*)d_in[1];
    const float* ln1_b     = (const float*)d_in[2];
    const float* attn_w    = (const float*)d_in[3];
    const float* ln2_g     = (const float*)d_in[4];
    const float* ln2_b     = (const float*)d_in[5];
    const float* gate_w    = (const float*)d_in[6];
    const float* gate_proj = (const float*)d_in[7];
    const float* up_proj   = (const float*)d_in[8];
    const float* down_proj = (const float*)d_in[9];
    float* out = (float*)d_out;

    cudaFuncSetAttribute(attn_f16, cudaFuncAttributeMaxDynamicSharedMemorySize, SMEMA);
    cudaFuncSetAttribute(mlp1_tc,  cudaFuncAttributeMaxDynamicSharedMemorySize, SMEM2);
    cudaFuncSetAttribute(mlp2_tc,  cudaFuncAttributeMaxDynamicSharedMemorySize, SMEM2);

    const int n4w = NE * INTER * H / 4;  // 8388608
    const int n4a = H * H / 4;           // 262144

    // Side stream: wsplit(+cnt zero) -> wconv gate/up -> wconv down.
    // Joins: eA before attn; eGU before mlp1; eD before mlp2.
    cudaStream_t s1;
    cudaStreamCreateWithFlags(&s1, cudaStreamNonBlocking);
    cudaEvent_t e0, eA, eGU, eD;
    cudaEventCreateWithFlags(&e0, cudaEventDisableTiming);
    cudaEventCreateWithFlags(&eA, cudaEventDisableTiming);
    cudaEventCreateWithFlags(&eGU, cudaEventDisableTiming);
    cudaEventCreateWithFlags(&eD, cudaEventDisableTiming);

    cudaEventRecord(e0, 0);                 // fork
    cudaStreamWaitEvent(s1, e0, 0);
    wsplit_k<<<n4a / 256, 256, 0, s1>>>((const float4*)attn_w, n4a);
    cudaEventRecord(eA, s1);                // attn weights + zeroed counters
    wconv_gu_k<<<dim3(n4w / 256, 2), 256, 0, s1>>>((const float4*)gate_proj,
                                                   (const float4*)up_proj, n4w);
    cudaEventRecord(eGU, s1);               // gate/up weights ready
    wconv_d_k<<<n4w / 256, 256, 0, s1>>>((const float4*)down_proj, n4w);
    cudaEventRecord(eD, s1);                // down weights ready

    ln1_kernel<<<TT, 256>>>(x, ln1_g, ln1_b);                       // tn hi/lo fp16
    cudaStreamWaitEvent(0, eA, 0);
    attn_f16<<<dim3(TT / 128, H / 128), 512, SMEMA>>>(x, out);      // out = h
    ln2_gate_kernel<<<TT, 256>>>(out, ln2_g, ln2_b, gate_w);        // g_tnh + routing
    build_tiles_k<<<1, 32>>>();
    cudaStreamWaitEvent(0, eGU, 0);
    mlp1_tc<<<dim3(MAXTILES, INTER / 64), 256, SMEM2>>>();
    cudaStreamWaitEvent(0, eD, 0);
    mlp2_tc<<<dim3(MAXTILES, H / 128), 256, SMEM2>>>();
    combine_kernel<<<(TT * H / 4) / 256, 256>>>(out);
}